// round 5
// baseline (speedup 1.0000x reference)
#include <cuda_runtime.h>
#include <cuda_bf16.h>

#define S_GRID 7
#define CH 30
#define TILE 1470            // 7*7*30 floats per image
#define MAXM 16
#define NUMC 20
#define IPB 4                // images per block
#define THREADS 256
#define MAXPART 4096         // >= B/IPB

__device__ float g_partial[MAXPART];
__device__ unsigned int g_count = 0;

// 32-byte evict_last load (sm_103 requires v8.b32 width for L2::evict_last).
__device__ __forceinline__ void ldg32_evict_last(const void* p, float4& a, float4& b) {
    asm volatile(
        "ld.global.nc.L2::evict_last.v8.b32 {%0,%1,%2,%3,%4,%5,%6,%7}, [%8];"
        : "=f"(a.x), "=f"(a.y), "=f"(a.z), "=f"(a.w),
          "=f"(b.x), "=f"(b.y), "=f"(b.z), "=f"(b.w)
        : "l"(p));
}

__device__ __forceinline__ float iou_fn(float a0, float a1, float a2, float a3,
                                        float b0, float b1, float b2, float b3) {
    float ax1 = a0 - a2 * 0.5f, ay1 = a1 - a3 * 0.5f;
    float ax2 = a0 + a2 * 0.5f, ay2 = a1 + a3 * 0.5f;
    float bx1 = b0 - b2 * 0.5f, by1 = b1 - b3 * 0.5f;
    float bx2 = b0 + b2 * 0.5f, by2 = b1 + b3 * 0.5f;
    float iw = fmaxf(fminf(ax2, bx2) - fmaxf(ax1, bx1), 0.0f);
    float ih = fmaxf(fminf(ay2, by2) - fmaxf(ay1, by1), 0.0f);
    float inter = iw * ih;
    float uni = a2 * a3 + b2 * b3 - inter;
    return inter / (uni + 1e-6f);
}

__device__ __forceinline__ float block_reduce_256(float v, float* s_red, int t) {
    #pragma unroll
    for (int off = 16; off > 0; off >>= 1)
        v += __shfl_down_sync(0xffffffffu, v, off);
    if ((t & 31) == 0) s_red[t >> 5] = v;
    __syncthreads();
    float r = 0.0f;
    #pragma unroll
    for (int i = 0; i < 8; i++) r += s_red[i];
    return r;
}

__global__ __launch_bounds__(THREADS) void yolo_loss_stream(
    const float* __restrict__ pred,
    const float* __restrict__ gt_xywh,
    const int*   __restrict__ gt_class,
    float* __restrict__ out,
    int nblk, int Btot) {

    const int t = threadIdx.x;
    const long long b0 = (long long)blockIdx.x * IPB;

    __shared__ float tile[IPB * TILE];           // 23520 B
    __shared__ int s_cell[IPB][MAXM];
    __shared__ unsigned long long s_obj[IPB];
    __shared__ float s_red[8];
    __shared__ int s_last;

    // ---- gt metadata: 64 boxes (4 images x 16), coalesced float4 ----
    float4 g; int cls = 0, cell = 0, row = 0, col = 0;
    if (t < IPB * MAXM) {
        g   = reinterpret_cast<const float4*>(gt_xywh)[(long long)blockIdx.x * 64 + t];
        cls = gt_class[(long long)blockIdx.x * 64 + t];
        // Faithful to reference: row from x, col from y.
        row = min(max((int)floorf(g.x * 7.0f), 0), S_GRID - 1);
        col = min(max((int)floorf(g.y * 7.0f), 0), S_GRID - 1);
        cell = row * S_GRID + col;
        s_cell[t >> 4][t & 15] = cell;
    }

    // ---- fully coalesced 32B-stream of 4 images (735 x 32B per block) ----
    // Block slice offset = blockIdx.x * 23520 B -> 32B aligned.
    const char* src = reinterpret_cast<const char*>(pred + b0 * TILE);
    float4* dst = reinterpret_cast<float4*>(tile);
    {
        const int n32 = (IPB * TILE * 4) / 32;   // 735
        #pragma unroll
        for (int i = t; i < n32; i += THREADS) {
            float4 a, b;
            ldg32_evict_last(src + (size_t)i * 32, a, b);
            dst[2 * i]     = a;
            dst[2 * i + 1] = b;
        }
    }
    __syncthreads();

    if (t < IPB) {
        unsigned long long msk = 0ull;
        #pragma unroll
        for (int i = 0; i < MAXM; i++) msk |= 1ull << s_cell[t][i];
        s_obj[t] = msk;
    }
    int keep = 0;
    if (t < IPB * MAXM) {
        keep = 1;
        const int img = t >> 4, m = t & 15;
        for (int i = 0; i < m; i++)
            if (s_cell[img][i] == cell) keep = 0;
    }
    __syncthreads();

    float acc = 0.0f;

    // ---- no-object confidence: 4 images x 49 cells x 2 channels = 392 ----
    #pragma unroll
    for (int it = 0; it < 2; it++) {
        int idx = t + it * THREADS;
        if (idx < IPB * 2 * S_GRID * S_GRID) {
            int img = idx / 98;
            int r   = idx - img * 98;
            int c   = r >> 1;
            int ch  = (r & 1) ? 9 : 4;
            float w = ((s_obj[img] >> c) & 1ull) ? 0.0f : 0.5f;
            float v = tile[img * TILE + c * CH + ch];
            acc += w * v * v;                    // LAMBDA_NOOBJ
        }
    }

    // ---- per-box terms ----
    if (keep) {
        const int img = t >> 4;
        float tx = g.x * 7.0f - (float)col;      // faithful x/y swap
        float ty = g.y * 7.0f - (float)row;
        float tw = sqrtf(g.z);
        float th = sqrtf(g.w);
        const float2* rp = reinterpret_cast<const float2*>(
            &tile[img * TILE + cell * CH]);      // even index -> float2 safe

        float2 v0 = rp[0], v1 = rp[1], v2 = rp[2], v3 = rp[3], v4 = rp[4];

        float i1 = iou_fn(v0.x, v0.y, v1.x, v1.y, tx, ty, tw, th);
        float i2 = iou_fn(v2.y, v3.x, v3.y, v4.x, tx, ty, tw, th);
        bool use2 = (i2 >= i1);
        float bx = use2 ? v2.y : v0.x;
        float by = use2 ? v3.x : v0.y;
        float bw = use2 ? v3.y : v1.x;
        float bh = use2 ? v4.x : v1.y;
        float sc = use2 ? v4.y : v2.x;
        float si = use2 ? i2   : i1;

        float d0 = bx - tx, d1 = by - ty, d2 = bw - tw, d3 = bh - th;
        acc += 5.0f * (d0 * d0 + d1 * d1 + d2 * d2 + d3 * d3);  // LAMBDA_COORD
        float dc = sc - si;
        acc += dc * dc;

        #pragma unroll
        for (int i = 0; i < 10; i++) {
            float2 v = rp[5 + i];
            float e0 = v.x - ((2 * i     == cls) ? 1.0f : 0.0f);
            float e1 = v.y - ((2 * i + 1 == cls) ? 1.0f : 0.0f);
            acc += e0 * e0 + e1 * e1;
        }
    }

    // ---- block partial ----
    float tot = block_reduce_256(acc, s_red, t);
    if (t == 0) g_partial[blockIdx.x] = tot;

    // ---- fused final reduction (last block) ----
    __threadfence();
    if (t == 0) {
        unsigned int ticket = atomicAdd(&g_count, 1u);
        s_last = (ticket == (unsigned int)(nblk - 1));
    }
    __syncthreads();
    if (s_last) {
        __threadfence();
        float s = 0.0f;
        for (int i = t; i < nblk; i += THREADS)
            s += __ldcg(&g_partial[i]);
        __syncthreads();
        float fin = block_reduce_256(s, s_red, t);
        if (t == 0) {
            out[0] = fin / (float)Btot;
            g_count = 0;
        }
    }
}

extern "C" void kernel_launch(void* const* d_in, const int* in_sizes, int n_in,
                              void* d_out, int out_size) {
    const float* pred    = (const float*)d_in[0];
    const float* gt_xywh = (const float*)d_in[1];
    const int*   gt_cls  = (const int*)d_in[2];
    float* out = (float*)d_out;

    int B = in_sizes[0] / TILE;     // 16384
    int nblk = B / IPB;             // 4096

    yolo_loss_stream<<<nblk, THREADS>>>(pred, gt_xywh, gt_cls, out, nblk, B);
}

// round 6
// speedup vs baseline: 1.8504x; 1.8504x over previous
#include <cuda_runtime.h>
#include <cuda_bf16.h>

#define S_GRID 7
#define CH 30
#define TILE 1470          // 7*7*30
#define MAXM 16
#define NUMC 20
#define IPB 8              // images per block
#define MAXPART 4096       // >= B/IPB

__device__ float g_partial[MAXPART];
__device__ unsigned int g_count = 0;

__device__ __forceinline__ float iou_fn(float a0, float a1, float a2, float a3,
                                        float b0, float b1, float b2, float b3) {
    float ax1 = a0 - a2 * 0.5f, ay1 = a1 - a3 * 0.5f;
    float ax2 = a0 + a2 * 0.5f, ay2 = a1 + a3 * 0.5f;
    float bx1 = b0 - b2 * 0.5f, by1 = b1 - b3 * 0.5f;
    float bx2 = b0 + b2 * 0.5f, by2 = b1 + b3 * 0.5f;
    float iw = fmaxf(fminf(ax2, bx2) - fmaxf(ax1, bx1), 0.0f);
    float ih = fmaxf(fminf(ay2, by2) - fmaxf(ay1, by1), 0.0f);
    float inter = iw * ih;
    float uni = a2 * a3 + b2 * b3 - inter;
    return inter / (uni + 1e-6f);
}

__device__ __forceinline__ float block_reduce_128(float v, float* s_red, int t) {
    #pragma unroll
    for (int off = 16; off > 0; off >>= 1)
        v += __shfl_down_sync(0xffffffffu, v, off);
    if ((t & 31) == 0) s_red[t >> 5] = v;
    __syncthreads();
    return s_red[0] + s_red[1] + s_red[2] + s_red[3];
}

__global__ __launch_bounds__(128) void yolo_loss_fused(
    const float* __restrict__ pred,
    const float* __restrict__ gt_xywh,
    const int*   __restrict__ gt_class,
    float* __restrict__ out,
    int nblk, int Btot) {

    const int t = threadIdx.x;
    const long long b0 = (long long)blockIdx.x * IPB;

    __shared__ int s_cell[IPB][MAXM];
    __shared__ unsigned long long s_obj[IPB];
    __shared__ float s_red[4];
    __shared__ int s_last;

    // ---- gt metadata: one box per thread (8 imgs x 16 boxes), coalesced ----
    float4 g = reinterpret_cast<const float4*>(gt_xywh)[(long long)blockIdx.x * 128 + t];
    int cls  = gt_class[(long long)blockIdx.x * 128 + t];
    const int img = t >> 4;        // 0..7
    const int m   = t & 15;        // 0..15
    // Faithful to reference: row from x, col from y.
    int row = min(max((int)floorf(g.x * 7.0f), 0), S_GRID - 1);
    int col = min(max((int)floorf(g.y * 7.0f), 0), S_GRID - 1);
    int cell = row * S_GRID + col;
    s_cell[img][m] = cell;
    __syncthreads();

    if (t < IPB) {
        unsigned long long msk = 0ull;
        #pragma unroll
        for (int i = 0; i < MAXM; i++) msk |= 1ull << s_cell[t][i];
        s_obj[t] = msk;
    }
    // first-occurrence-per-cell dedup
    int keep = 1;
    for (int i = 0; i < m; i++)
        if (s_cell[img][i] == cell) keep = 0;
    __syncthreads();

    float acc = 0.0f;

    // ---- no-object confidence: 8 imgs x 49 cells x 2 ch = 784 items over
    //      128 threads, 7-deep unconditional loads (weight-masked) ----
    {
        const float* base = pred + b0 * TILE;
        float v[7]; float w[7];
        #pragma unroll
        for (int k = 0; k < 7; k++) {
            int idx = t + k * 128;
            bool ok = (idx < IPB * 98);
            int i  = idx / 98;              // image (const-div -> mul.hi)
            int r  = idx - i * 98;          // 0..97
            int c  = r >> 1;
            int ch = (r & 1) ? 9 : 4;
            i  = ok ? i : 0;
            c  = ok ? c : 0;
            // unconditional load: always a valid address; weight 0 if object cell
            v[k] = __ldg(base + i * TILE + c * CH + ch);
            w[k] = (!ok || ((s_obj[i] >> c) & 1ull)) ? 0.0f : 0.5f;   // LAMBDA_NOOBJ
        }
        #pragma unroll
        for (int k = 0; k < 7; k++)
            acc += w[k] * v[k] * v[k];
    }

    // ---- per-box terms: thread t owns (img, m) ----
    if (keep) {
        float tx = g.x * 7.0f - (float)col;      // faithful x/y swap
        float ty = g.y * 7.0f - (float)row;
        float tw = sqrtf(g.z);
        float th = sqrtf(g.w);
        const float2* rp = reinterpret_cast<const float2*>(
            &pred[(b0 + img) * TILE + cell * CH]);   // 8B-aligned row

        float2 v0 = __ldg(&rp[0]);   // ch0,1
        float2 v1 = __ldg(&rp[1]);   // ch2,3
        float2 v2 = __ldg(&rp[2]);   // ch4,5
        float2 v3 = __ldg(&rp[3]);   // ch6,7
        float2 v4 = __ldg(&rp[4]);   // ch8,9

        float i1 = iou_fn(v0.x, v0.y, v1.x, v1.y, tx, ty, tw, th);
        float i2 = iou_fn(v2.y, v3.x, v3.y, v4.x, tx, ty, tw, th);
        bool use2 = (i2 >= i1);
        float bx = use2 ? v2.y : v0.x;
        float by = use2 ? v3.x : v0.y;
        float bw = use2 ? v3.y : v1.x;
        float bh = use2 ? v4.x : v1.y;
        float sc = use2 ? v4.y : v2.x;
        float si = use2 ? i2   : i1;

        float d0 = bx - tx, d1 = by - ty, d2 = bw - tw, d3 = bh - th;
        acc += 5.0f * (d0 * d0 + d1 * d1 + d2 * d2 + d3 * d3);  // LAMBDA_COORD
        float dc = sc - si;
        acc += dc * dc;

        // classes: channels 10..29, streamed as float2
        #pragma unroll
        for (int i = 0; i < 10; i++) {
            float2 v = __ldg(&rp[5 + i]);
            float e0 = v.x - ((2 * i     == cls) ? 1.0f : 0.0f);
            float e1 = v.y - ((2 * i + 1 == cls) ? 1.0f : 0.0f);
            acc += e0 * e0 + e1 * e1;
        }
    }

    // ---- block partial ----
    float tot = block_reduce_128(acc, s_red, t);
    if (t == 0) g_partial[blockIdx.x] = tot;

    // ---- fused final reduction: last block finishes ----
    __threadfence();
    if (t == 0) {
        unsigned int ticket = atomicAdd(&g_count, 1u);
        s_last = (ticket == (unsigned int)(nblk - 1));
    }
    __syncthreads();
    if (s_last) {
        __threadfence();
        float s = 0.0f;
        for (int i = t; i < nblk; i += 128)
            s += __ldcg(&g_partial[i]);
        __syncthreads();          // s_red reuse
        float fin = block_reduce_128(s, s_red, t);
        if (t == 0) {
            out[0] = fin / (float)Btot;
            g_count = 0;          // ready for next (replay) launch
        }
    }
}

extern "C" void kernel_launch(void* const* d_in, const int* in_sizes, int n_in,
                              void* d_out, int out_size) {
    const float* pred    = (const float*)d_in[0];
    const float* gt_xywh = (const float*)d_in[1];
    const int*   gt_cls  = (const int*)d_in[2];
    float* out = (float*)d_out;

    int B = in_sizes[0] / TILE;     // 16384
    int nblk = B / IPB;             // 2048

    yolo_loss_fused<<<nblk, 128>>>(pred, gt_xywh, gt_cls, out, nblk, B);
}